// round 14
// baseline (speedup 1.0000x reference)
#include <cuda_runtime.h>
#include <cuda_bf16.h>
#include <cstdint>
#include <math.h>

#define HIDDEN 1024
#define NHEADS 16
#define HEADD  64
#define BATCH  4
#define SEQ    2048
#define MTOK   (BATCH*SEQ)
#define BNH    (BATCH*NHEADS)

// packed bf16 hi/lo pairs as u32
__device__ __align__(16) uint32_t g_Xh[MTOK*512],  g_Xl[MTOK*512];   // x
__device__ __align__(16) uint32_t g_XPh[MTOK*512], g_XPl[MTOK*512]; // x + pos
__device__ __align__(16) uint32_t g_WTh[3*HIDDEN*512], g_WTl[3*HIDDEN*512];
__device__ __align__(16) uint32_t g_WoTh[HIDDEN*512],  g_WoTl[HIDDEN*512];
__device__ __align__(16) uint32_t g_Qh[BNH*SEQ*32], g_Ql[BNH*SEQ*32];
__device__ __align__(16) uint32_t g_Kh[BNH*SEQ*32], g_Kl[BNH*SEQ*32];
__device__ __align__(16) uint32_t g_VTh[BNH*HEADD*1024], g_VTl[BNH*HEADD*1024];
__device__ __align__(16) uint32_t g_Oh[BNH*SEQ*32], g_Ol[BNH*SEQ*32];

__device__ __forceinline__ void split_pack(float a, float b, uint32_t& hi, uint32_t& lo) {
    __nv_bfloat16 ah = __float2bfloat16(a);
    __nv_bfloat16 bh = __float2bfloat16(b);
    __nv_bfloat16 al = __float2bfloat16(a - __bfloat162float(ah));
    __nv_bfloat16 bl = __float2bfloat16(b - __bfloat162float(bh));
    hi = (uint32_t)__bfloat16_as_ushort(ah) | ((uint32_t)__bfloat16_as_ushort(bh) << 16);
    lo = (uint32_t)__bfloat16_as_ushort(al) | ((uint32_t)__bfloat16_as_ushort(bl) << 16);
}

__device__ __forceinline__ void mma16816(float c[4], const uint32_t a[4],
                                         uint32_t b0, uint32_t b1) {
    asm volatile(
        "mma.sync.aligned.m16n8k16.row.col.f32.bf16.bf16.f32 "
        "{%0,%1,%2,%3},{%4,%5,%6,%7},{%8,%9},{%0,%1,%2,%3};\n"
        : "+f"(c[0]), "+f"(c[1]), "+f"(c[2]), "+f"(c[3])
        : "r"(a[0]), "r"(a[1]), "r"(a[2]), "r"(a[3]), "r"(b0), "r"(b1));
}

__device__ __forceinline__ void ldsm4(uint32_t r[4], uint32_t addr) {
    asm volatile("ldmatrix.sync.aligned.m8n8.x4.shared.b16 {%0,%1,%2,%3}, [%4];\n"
                 : "=r"(r[0]), "=r"(r[1]), "=r"(r[2]), "=r"(r[3]) : "r"(addr));
}

__device__ __forceinline__ void cpa(uint32_t saddr, const void* g) {
    asm volatile("cp.async.cg.shared.global [%0], [%1], 16;\n" :: "r"(saddr), "l"(g) : "memory");
}
#define CPCOMMIT() asm volatile("cp.async.commit_group;\n" ::: "memory")
#define CPWAIT1()  asm volatile("cp.async.wait_group 1;\n" ::: "memory")

// cvt: x pairs AND (x+pos) pairs in one pass
__global__ void cvt_x_kernel(const float* __restrict__ x, const float* __restrict__ pe) {
    int i = blockIdx.x * blockDim.x + threadIdx.x;
    if (i < MTOK * 512) {
        float2 v = ((const float2*)x)[i];
        split_pack(v.x, v.y, g_Xh[i], g_Xl[i]);
        int m = i >> 9, c = i & 511;
        int s = m & (SEQ - 1);
        float2 p = ((const float2*)pe)[s * 512 + c];
        split_pack(v.x + p.x, v.y + p.y, g_XPh[i], g_XPl[i]);
    }
}

__global__ void cvt_w_kernel(const float* __restrict__ Wqkv, const float* __restrict__ Wo) {
    int i = blockIdx.x * blockDim.x + threadIdx.x;
    const int N1 = 3 * HIDDEN * 512, N2 = HIDDEN * 512;
    if (i < N1) {
        int n = i % (3 * HIDDEN), kp = i / (3 * HIDDEN);
        split_pack(Wqkv[(size_t)(2 * kp) * 3072 + n], Wqkv[(size_t)(2 * kp + 1) * 3072 + n],
                   g_WTh[(size_t)n * 512 + kp], g_WTl[(size_t)n * 512 + kp]);
    } else if (i < N1 + N2) {
        int j = i - N1;
        int n = j % HIDDEN, kp = j / HIDDEN;
        split_pack(Wo[(size_t)(2 * kp) * HIDDEN + n], Wo[(size_t)(2 * kp + 1) * HIDDEN + n],
                   g_WoTh[(size_t)n * 512 + kp], g_WoTl[(size_t)n * 512 + kp]);
    }
}

// ---------------- GEMM: 128x128 tile, K-step 32 floats, cp.async 2-stage ----
extern __shared__ __align__(16) uint32_t dynsm[];

#define GEMM_PROLOG()                                                          \
    const int tid = threadIdx.x, lane = tid & 31, wid = tid >> 5;              \
    const int g = lane >> 2, tig = lane & 3;                                   \
    const int wm = wid >> 2, wn = wid & 3;                                     \
    const int m0 = blockIdx.y * 128, n0 = blockIdx.x * 128;                    \
    const uint32_t sbase = (uint32_t)__cvta_generic_to_shared(dynsm);          \
    const int row = tid >> 2, cc = (tid & 3) * 4;                              \
    const uint32_t dA0 = (uint32_t)(row * 20 + cc) * 4, dA1 = dA0 + 5120;      \
    const uint32_t foB = (uint32_t)(((lane & 7) + 8 * ((lane >> 3) & 1)) * 20  \
                                    + 4 * (lane >> 4)) * 4;                    \
    const uint32_t aB = (uint32_t)wm * 5120 + foB;                             \
    const uint32_t bB = (uint32_t)wn * 2560 + foB;                             \
    float acc[4][4][4];                                                        \
    for (int a_ = 0; a_ < 4; a_++)                                             \
        for (int b_ = 0; b_ < 4; b_++)                                         \
            for (int c_ = 0; c_ < 4; c_++) acc[a_][b_][c_] = 0.f;

// term-major mma order: each accumulator touched 3x with 15 mmas between
#define GEMM_COMPUTE(bo)                                                       \
    _Pragma("unroll")                                                          \
    for (int ks = 0; ks < 2; ks++) {                                           \
        uint32_t ah[4][4], al[4][4], t0[4], t1[4], u0[4], u1[4];               \
        _Pragma("unroll")                                                      \
        for (int mi = 0; mi < 4; mi++) {                                       \
            ldsm4(ah[mi], sbase + (bo) + aB + mi * 1280 + ks * 32);            \
            ldsm4(al[mi], sbase + (bo) + 10240 + aB + mi * 1280 + ks * 32);    \
        }                                                                      \
        ldsm4(t0, sbase + (bo) + 20480 + bB + ks * 32);                        \
        ldsm4(t1, sbase + (bo) + 20480 + bB + 1280 + ks * 32);                 \
        ldsm4(u0, sbase + (bo) + 30720 + bB + ks * 32);                        \
        ldsm4(u1, sbase + (bo) + 30720 + bB + 1280 + ks * 32);                 \
        _Pragma("unroll")                                                      \
        for (int mi = 0; mi < 4; mi++) {                                       \
            mma16816(acc[mi][0], ah[mi], t0[0], t0[2]);                        \
            mma16816(acc[mi][1], ah[mi], t0[1], t0[3]);                        \
            mma16816(acc[mi][2], ah[mi], t1[0], t1[2]);                        \
            mma16816(acc[mi][3], ah[mi], t1[1], t1[3]);                        \
        }                                                                      \
        _Pragma("unroll")                                                      \
        for (int mi = 0; mi < 4; mi++) {                                       \
            mma16816(acc[mi][0], al[mi], t0[0], t0[2]);                        \
            mma16816(acc[mi][1], al[mi], t0[1], t0[3]);                        \
            mma16816(acc[mi][2], al[mi], t1[0], t1[2]);                        \
            mma16816(acc[mi][3], al[mi], t1[1], t1[3]);                        \
        }                                                                      \
        _Pragma("unroll")                                                      \
        for (int mi = 0; mi < 4; mi++) {                                       \
            mma16816(acc[mi][0], ah[mi], u0[0], u0[2]);                        \
            mma16816(acc[mi][1], ah[mi], u0[1], u0[3]);                        \
            mma16816(acc[mi][2], ah[mi], u1[0], u1[2]);                        \
            mma16816(acc[mi][3], ah[mi], u1[1], u1[3]);                        \
        }                                                                      \
    }

#define MAINLOOP_PIPE(STAGE)                                                   \
    STAGE(0, 0); CPCOMMIT();                                                   \
    for (int kt = 0; kt < 32; kt++) {                                          \
        if (kt + 1 < 32) { STAGE((kt + 1), ((kt + 1) & 1)); }                  \
        CPCOMMIT();                                                            \
        CPWAIT1(); __syncthreads();                                            \
        GEMM_COMPUTE((uint32_t)(kt & 1) * 40960u);                             \
        __syncthreads();                                                       \
    }

#define STAGE_STD(kt, b)                                                       \
    { uint32_t sb = sbase + (uint32_t)(b) * 40960u;                            \
      int off = (kt) * 16;                                                     \
      cpa(sb + dA0,          pAh0 + off);                                      \
      cpa(sb + dA1,          pAh1 + off);                                      \
      cpa(sb + 10240 + dA0,  pAl0 + off);                                      \
      cpa(sb + 10240 + dA1,  pAl1 + off);                                      \
      cpa(sb + 20480 + dA0,  pBh0 + off);                                      \
      cpa(sb + 20480 + dA1,  pBh1 + off);                                      \
      cpa(sb + 30720 + dA0,  pBl0 + off);                                      \
      cpa(sb + 30720 + dA1,  pBl1 + off); }

__global__ __launch_bounds__(256, 2) void qkv_gemm() {
    GEMM_PROLOG();
    const int reg = n0 >> 10;   // 0=Q 1=K 2=V, uniform per block
    const uint32_t* baseAh = (reg < 2) ? g_XPh : g_Xh;
    const uint32_t* baseAl = (reg < 2) ? g_XPl : g_Xl;
    const uint32_t* pAh0 = baseAh + (size_t)(m0 + row) * 512 + cc;
    const uint32_t* pAh1 = baseAh + (size_t)(m0 + row + 64) * 512 + cc;
    const uint32_t* pAl0 = baseAl + (size_t)(m0 + row) * 512 + cc;
    const uint32_t* pAl1 = baseAl + (size_t)(m0 + row + 64) * 512 + cc;
    const uint32_t* pBh0 = g_WTh + (size_t)(n0 + row) * 512 + cc;
    const uint32_t* pBh1 = g_WTh + (size_t)(n0 + row + 64) * 512 + cc;
    const uint32_t* pBl0 = g_WTl + (size_t)(n0 + row) * 512 + cc;
    const uint32_t* pBl1 = g_WTl + (size_t)(n0 + row + 64) * 512 + cc;
    MAINLOOP_PIPE(STAGE_STD);

#pragma unroll
    for (int mi = 0; mi < 4; mi++) {
#pragma unroll
        for (int nj = 0; nj < 4; nj++) {
            int m = m0 + wm * 64 + mi * 16 + g;
            int nn = n0 + wn * 32 + nj * 8 + 2 * tig;
            int bb = m >> 11, ss = m & 2047;
            float c0 = acc[mi][nj][0], c1 = acc[mi][nj][1];
            float c2 = acc[mi][nj][2], c3 = acc[mi][nj][3];
            if (reg < 2) {
                if (reg == 0) { c0 *= 0.125f; c1 *= 0.125f; c2 *= 0.125f; c3 *= 0.125f; }
                int head = (nn >> 6) & 15, hp = (nn & 63) >> 1;
                size_t bn = (size_t)bb * 16 + head;
                size_t i0 = (bn * SEQ + ss) * 32 + hp;
                size_t i1 = (bn * SEQ + ss + 8) * 32 + hp;
                uint32_t h01, l01, h23, l23;
                split_pack(c0, c1, h01, l01);
                split_pack(c2, c3, h23, l23);
                if (reg == 0) { g_Qh[i0] = h01; g_Ql[i0] = l01; g_Qh[i1] = h23; g_Ql[i1] = l23; }
                else          { g_Kh[i0] = h01; g_Kl[i0] = l01; g_Kh[i1] = h23; g_Kl[i1] = l23; }
            } else {
                float o0 = __shfl_xor_sync(0xffffffffu, c0, 4);
                float o1 = __shfl_xor_sync(0xffffffffu, c1, 4);
                float o2 = __shfl_xor_sync(0xffffffffu, c2, 4);
                float o3 = __shfl_xor_sync(0xffffffffu, c3, 4);
                if ((g & 1) == 0) {
                    int head = (nn >> 6) & 15;
                    size_t bn = (size_t)bb * 16 + head;
                    int h0 = nn & 63;
                    int sp0 = ss >> 1;
                    uint32_t hi, lo;
                    size_t b0 = (bn * HEADD + h0) * 1024;
                    size_t b1 = (bn * HEADD + h0 + 1) * 1024;
                    split_pack(c0, o0, hi, lo); g_VTh[b0 + sp0] = hi;     g_VTl[b0 + sp0] = lo;
                    split_pack(c1, o1, hi, lo); g_VTh[b1 + sp0] = hi;     g_VTl[b1 + sp0] = lo;
                    split_pack(c2, o2, hi, lo); g_VTh[b0 + sp0 + 4] = hi; g_VTl[b0 + sp0 + 4] = lo;
                    split_pack(c3, o3, hi, lo); g_VTh[b1 + sp0 + 4] = hi; g_VTl[b1 + sp0 + 4] = lo;
                }
            }
        }
    }
}

#define STAGE_OUT(kt, b)                                                       \
    { uint32_t sb = sbase + (uint32_t)(b) * 40960u;                            \
      int head = (kt) >> 1;                                                    \
      int wv = ((kt) & 1) * 16 + cc;                                           \
      const uint32_t* a0h = g_Oh + baseO + (size_t)head * (SEQ * 32) + wv;     \
      const uint32_t* a0l = g_Ol + baseO + (size_t)head * (SEQ * 32) + wv;     \
      cpa(sb + dA0,          a0h);                                             \
      cpa(sb + dA1,          a0h + 64 * 32);                                   \
      cpa(sb + 10240 + dA0,  a0l);                                             \
      cpa(sb + 10240 + dA1,  a0l + 64 * 32);                                   \
      int off = (kt) * 16;                                                     \
      cpa(sb + 20480 + dA0,  pBh0 + off);                                      \
      cpa(sb + 20480 + dA1,  pBh1 + off);                                      \
      cpa(sb + 30720 + dA0,  pBl0 + off);                                      \
      cpa(sb + 30720 + dA1,  pBl1 + off); }

__global__ __launch_bounds__(256, 2) void out_gemm(float* __restrict__ out) {
    GEMM_PROLOG();
    const int arow = m0 + row;
    const int bb = arow >> 11, ss = arow & 2047;
    const size_t baseO = ((size_t)bb * 16 * SEQ + ss) * 32;
    const uint32_t* pBh0 = g_WoTh + (size_t)(n0 + row) * 512 + cc;
    const uint32_t* pBh1 = g_WoTh + (size_t)(n0 + row + 64) * 512 + cc;
    const uint32_t* pBl0 = g_WoTl + (size_t)(n0 + row) * 512 + cc;
    const uint32_t* pBl1 = g_WoTl + (size_t)(n0 + row + 64) * 512 + cc;
    MAINLOOP_PIPE(STAGE_OUT);
#pragma unroll
    for (int mi = 0; mi < 4; mi++)
#pragma unroll
        for (int nj = 0; nj < 4; nj++) {
            int m = m0 + wm * 64 + mi * 16 + g;
            int nn = n0 + wn * 32 + nj * 8 + 2 * tig;
            *(float2*)(out + (size_t)m * HIDDEN + nn) = make_float2(acc[mi][nj][0], acc[mi][nj][1]);
            *(float2*)(out + (size_t)(m + 8) * HIDDEN + nn) = make_float2(acc[mi][nj][2], acc[mi][nj][3]);
        }
}

// ---------------- flash attention: 128-query blocks, 8 warps --------------
#define ATTN_SMEM 90112

__global__ __launch_bounds__(256, 2) void attn_kernel() {
    uint32_t* Kh = dynsm;
    uint32_t* Kl = dynsm + 2816;
    uint32_t* Vh = dynsm + 5632;
    uint32_t* Vl = dynsm + 8448;
    uint32_t* Ph = dynsm + 11264;
    uint32_t* Pl = dynsm + 16896;

    const int tid = threadIdx.x, lane = tid & 31, w = tid >> 5;
    const int g = lane >> 2, tig = lane & 3;
    const int bn = blockIdx.x, qb = blockIdx.y;

    const uint32_t sbase = (uint32_t)__cvta_generic_to_shared(dynsm);
    const uint32_t sKh = sbase,          sKl = sbase + 11264;
    const uint32_t sVh = sbase + 22528,  sVl = sbase + 33792;
    const uint32_t sPh = sbase + 45056,  sPl = sbase + 67584;
    const uint32_t foA = (uint32_t)(((lane & 7) + 8 * ((lane >> 3) & 1)) * 176 + 16 * (lane >> 4));

    const int qr = qb * 128 + 16 * w + g;
    const uint32_t* qbh = g_Qh + ((size_t)bn * SEQ + qr) * 32 + tig;
    const uint32_t* qbl = g_Ql + ((size_t)bn * SEQ + qr) * 32 + tig;
    uint32_t qah[4][4], qal[4][4];
#pragma unroll
    for (int ks = 0; ks < 4; ks++) {
        qah[ks][0] = qbh[ks * 8];     qah[ks][1] = qbh[256 + ks * 8];
        qah[ks][2] = qbh[ks * 8 + 4]; qah[ks][3] = qbh[256 + ks * 8 + 4];
        qal[ks][0] = qbl[ks * 8];     qal[ks][1] = qbl[256 + ks * 8];
        qal[ks][2] = qbl[ks * 8 + 4]; qal[ks][3] = qbl[256 + ks * 8 + 4];
    }

    float o[8][4];
#pragma unroll
    for (int nt = 0; nt < 8; nt++)
#pragma unroll
        for (int c = 0; c < 4; c++) o[nt][c] = 0.f;
    float mrun0 = -1e30f, mrun1 = -1e30f, lrun0 = 0.f, lrun1 = 0.f;

    const int lrow = tid >> 2, cb = (tid & 3) * 8;
    const int sidx = lrow * 44 + cb;
    const uint32_t* kgh = g_Kh + ((size_t)bn * SEQ + lrow) * 32 + cb;
    const uint32_t* kgl = g_Kl + ((size_t)bn * SEQ + lrow) * 32 + cb;
    const uint32_t* vgh = g_VTh + ((size_t)bn * HEADD + lrow) * 1024 + cb;
    const uint32_t* vgl = g_VTl + ((size_t)bn * HEADD + lrow) * 1024 + cb;

    const int ntiles = 2 * qb + 2;
    for (int kt = 0; kt < ntiles; kt++) {
        const int kbase = kt * 64;
        __syncthreads();
        {
            size_t ko = (size_t)kbase * 32, vo = (size_t)kt * 32;
            *(uint4*)&Kh[sidx]     = *(const uint4*)(kgh + ko);
            *(uint4*)&Kh[sidx + 4] = *(const uint4*)(kgh + ko + 4);
            *(uint4*)&Kl[sidx]     = *(const uint4*)(kgl + ko);
            *(uint4*)&Kl[sidx + 4] = *(const uint4*)(kgl + ko + 4);
            *(uint4*)&Vh[sidx]     = *(const uint4*)(vgh + vo);
            *(uint4*)&Vh[sidx + 4] = *(const uint4*)(vgh + vo + 4);
            *(uint4*)&Vl[sidx]     = *(const uint4*)(vgl + vo);
            *(uint4*)&Vl[sidx + 4] = *(const uint4*)(vgl + vo + 4);
        }
        __syncthreads();

        // S = Qs @ K^T  (pairwise m, term-major: 4 independent chains, gap-3)
        float sacc[8][4];
#pragma unroll
        for (int nt = 0; nt < 8; nt++)
#pragma unroll
            for (int c = 0; c < 4; c++) sacc[nt][c] = 0.f;
#pragma unroll
        for (int ks = 0; ks < 4; ks++) {
#pragma unroll
            for (int mp = 0; mp < 4; mp += 2) {
                uint32_t tka[4], uka[4], tkb[4], ukb[4];
                ldsm4(tka, sKh + mp * 2816 + ks * 32 + foA);
                ldsm4(uka, sKl + mp * 2816 + ks * 32 + foA);
                ldsm4(tkb, sKh + (mp + 1) * 2816 + ks * 32 + foA);
                ldsm4(ukb, sKl + (mp + 1) * 2816 + ks * 32 + foA);
                mma16816(sacc[2 * mp],     qah[ks], tka[0], tka[2]);
                mma16816(sacc[2 * mp + 1], qah[ks], tka[1], tka[3]);
                mma16816(sacc[2 * mp + 2], qah[ks], tkb[0], tkb[2]);
                mma16816(sacc[2 * mp + 3], qah[ks], tkb[1], tkb[3]);
                mma16816(sacc[2 * mp],     qal[ks], tka[0], tka[2]);
                mma16816(sacc[2 * mp + 1], qal[ks], tka[1], tka[3]);
                mma16816(sacc[2 * mp + 2], qal[ks], tkb[0], tkb[2]);
                mma16816(sacc[2 * mp + 3], qal[ks], tkb[1], tkb[3]);
                mma16816(sacc[2 * mp],     qah[ks], uka[0], uka[2]);
                mma16816(sacc[2 * mp + 1], qah[ks], uka[1], uka[3]);
                mma16816(sacc[2 * mp + 2], qah[ks], ukb[0], ukb[2]);
                mma16816(sacc[2 * mp + 3], qah[ks], ukb[1], ukb[3]);
            }
        }

        if (kbase + 63 > qr) {
#pragma unroll
            for (int nt = 0; nt < 8; nt++) {
                int kg = kbase + nt * 8 + 2 * tig;
                if (kg > qr)         sacc[nt][0] = -1e30f;
                if (kg + 1 > qr)     sacc[nt][1] = -1e30f;
                if (kg > qr + 8)     sacc[nt][2] = -1e30f;
                if (kg + 1 > qr + 8) sacc[nt][3] = -1e30f;
            }
        }

        // online softmax
        float ml0 = -1e30f, ml1 = -1e30f;
#pragma unroll
        for (int nt = 0; nt < 8; nt++) {
            ml0 = fmaxf(ml0, fmaxf(sacc[nt][0], sacc[nt][1]));
            ml1 = fmaxf(ml1, fmaxf(sacc[nt][2], sacc[nt][3]));
        }
        ml0 = fmaxf(ml0, __shfl_xor_sync(0xffffffffu, ml0, 1));
        ml0 = fmaxf(ml0, __shfl_xor_sync(0xffffffffu, ml0, 2));
        ml1 = fmaxf(ml1, __shfl_xor_sync(0xffffffffu, ml1, 1));
        ml1 = fmaxf(ml1, __shfl_xor_sync(0xffffffffu, ml1, 2));
        float mn0 = fmaxf(mrun0, ml0), mn1 = fmaxf(mrun1, ml1);
        float scl0 = __expf(mrun0 - mn0), scl1 = __expf(mrun1 - mn1);
        mrun0 = mn0; mrun1 = mn1;
        float ls0 = 0.f, ls1 = 0.f;
#pragma unroll
        for (int nt = 0; nt < 8; nt++) {
            float p0 = __expf(sacc[nt][0] - mn0);
            float p1 = __expf(sacc[nt][1] - mn0);
            float p2 = __expf(sacc[nt][2] - mn1);
            float p3 = __expf(sacc[nt][3] - mn1);
            ls0 += p0 + p1; ls1 += p2 + p3;
            sacc[nt][0] = p0; sacc[nt][1] = p1; sacc[nt][2] = p2; sacc[nt][3] = p3;
            o[nt][0] *= scl0; o[nt][1] *= scl0; o[nt][2] *= scl1; o[nt][3] *= scl1;
        }
        lrun0 = lrun0 * scl0 + ls0;
        lrun1 = lrun1 * scl1 + ls1;

        // P store: dedicated buffer, rows warp-private
#pragma unroll
        for (int nt = 0; nt < 8; nt++) {
            uint32_t hi, lo;
            split_pack(sacc[nt][0], sacc[nt][1], hi, lo);
            Ph[(16 * w + g) * 44 + nt * 4 + tig] = hi;
            Pl[(16 * w + g) * 44 + nt * 4 + tig] = lo;
            split_pack(sacc[nt][2], sacc[nt][3], hi, lo);
            Ph[(16 * w + g + 8) * 44 + nt * 4 + tig] = hi;
            Pl[(16 * w + g + 8) * 44 + nt * 4 + tig] = lo;
        }
        __syncwarp();

        // O += P @ V  (pairwise m, term-major)
#pragma unroll
        for (int ks = 0; ks < 4; ks++) {
            uint32_t ph[4], pl[4];
            ldsm4(ph, sPh + w * 2816 + ks * 32 + foA);
            ldsm4(pl, sPl + w * 2816 + ks * 32 + foA);
#pragma unroll
            for (int mp = 0; mp < 4; mp += 2) {
                uint32_t tva[4], uva[4], tvb[4], uvb[4];
                ldsm4(tva, sVh + mp * 2816 + ks * 32 + foA);
                ldsm4(uva, sVl + mp * 2816 + ks * 32 + foA);
                ldsm4(tvb, sVh + (mp + 1) * 2816 + ks * 32 + foA);
                ldsm4(uvb, sVl + (mp + 1) * 2816 + ks * 32 + foA);
                mma16816(o[2 * mp],     ph, tva[0], tva[2]);
                mma16816(o[2 * mp + 1], ph, tva[1], tva[3]);
                mma16816(o[2 * mp + 2], ph, tvb[0], tvb[2]);
                mma16816(o[2 * mp + 3], ph, tvb[1], tvb[3]);
                mma16816(o[2 * mp],     pl, tva[0], tva[2]);
                mma16816(o[2 * mp + 1], pl, tva[1], tva[3]);
                mma16816(o[2 * mp + 2], pl, tvb[0], tvb[2]);
                mma16816(o[2 * mp + 3], pl, tvb[1], tvb[3]);
                mma16816(o[2 * mp],     ph, uva[0], uva[2]);
                mma16816(o[2 * mp + 1], ph, uva[1], uva[3]);
                mma16816(o[2 * mp + 2], ph, uvb[0], uvb[2]);
                mma16816(o[2 * mp + 3], ph, uvb[1], uvb[3]);
            }
        }
    }

    lrun0 += __shfl_xor_sync(0xffffffffu, lrun0, 1);
    lrun0 += __shfl_xor_sync(0xffffffffu, lrun0, 2);
    lrun1 += __shfl_xor_sync(0xffffffffu, lrun1, 1);
    lrun1 += __shfl_xor_sync(0xffffffffu, lrun1, 2);
    float inv0 = 1.f / lrun0, inv1 = 1.f / lrun1;
    size_t ob0 = ((size_t)bn * SEQ + qr) * 32 + tig;
    size_t ob1 = ((size_t)bn * SEQ + qr + 8) * 32 + tig;
#pragma unroll
    for (int nt = 0; nt < 8; nt++) {
        uint32_t hi, lo;
        split_pack(o[nt][0] * inv0, o[nt][1] * inv0, hi, lo);
        g_Oh[ob0 + nt * 4] = hi;  g_Ol[ob0 + nt * 4] = lo;
        split_pack(o[nt][2] * inv1, o[nt][3] * inv1, hi, lo);
        g_Oh[ob1 + nt * 4] = hi;  g_Ol[ob1 + nt * 4] = lo;
    }
}

extern "C" void kernel_launch(void* const* d_in, const int* in_sizes, int n_in,
                              void* d_out, int out_size)
{
    const float* x    = (const float*)d_in[0];
    const float* pe   = (const float*)d_in[1];
    const float* Wqkv = (const float*)d_in[2];
    const float* Wo   = (const float*)d_in[3];
    float* out = (float*)d_out;

    const int SMEM_DYN = 2 * 40960;
    cudaFuncSetAttribute(qkv_gemm, cudaFuncAttributeMaxDynamicSharedMemorySize, SMEM_DYN);
    cudaFuncSetAttribute(out_gemm, cudaFuncAttributeMaxDynamicSharedMemorySize, SMEM_DYN);
    cudaFuncSetAttribute(attn_kernel, cudaFuncAttributeMaxDynamicSharedMemorySize, ATTN_SMEM);

    cvt_x_kernel<<<(MTOK * 512 + 255) / 256, 256>>>(x, pe);
    cvt_w_kernel<<<(4 * HIDDEN * 512 + 255) / 256, 256>>>(Wqkv, Wo);
    qkv_gemm<<<dim3(3 * HIDDEN / 128, MTOK / 128), 256, SMEM_DYN>>>();
    attn_kernel<<<dim3(BNH, SEQ / 128), 256, ATTN_SMEM>>>();
    out_gemm<<<dim3(HIDDEN / 128, MTOK / 128), 256, SMEM_DYN>>>(out);
}

// round 16
// speedup vs baseline: 1.0672x; 1.0672x over previous
#include <cuda_runtime.h>
#include <cuda_bf16.h>
#include <cstdint>
#include <math.h>

#define HIDDEN 1024
#define NHEADS 16
#define HEADD  64
#define BATCH  4
#define SEQ    2048
#define MTOK   (BATCH*SEQ)
#define BNH    (BATCH*NHEADS)

// Q scale folded with log2(e): 0.125 * 1.4426950408889634
#define QSCALE 0.18033688011112042f

// packed bf16 hi/lo pairs as u32
__device__ __align__(16) uint32_t g_Xh[MTOK*512],  g_Xl[MTOK*512];   // x
__device__ __align__(16) uint32_t g_XPh[MTOK*512], g_XPl[MTOK*512]; // x + pos
__device__ __align__(16) uint32_t g_WTh[3*HIDDEN*512], g_WTl[3*HIDDEN*512];
__device__ __align__(16) uint32_t g_WoTh[HIDDEN*512],  g_WoTl[HIDDEN*512];
__device__ __align__(16) uint32_t g_Qh[BNH*SEQ*32], g_Ql[BNH*SEQ*32];
__device__ __align__(16) uint32_t g_Kh[BNH*SEQ*32], g_Kl[BNH*SEQ*32];
__device__ __align__(16) uint32_t g_VTh[BNH*HEADD*1024], g_VTl[BNH*HEADD*1024];
__device__ __align__(16) uint32_t g_Oh[BNH*SEQ*32], g_Ol[BNH*SEQ*32];

__device__ __forceinline__ void split_pack(float a, float b, uint32_t& hi, uint32_t& lo) {
    __nv_bfloat16 ah = __float2bfloat16(a);
    __nv_bfloat16 bh = __float2bfloat16(b);
    __nv_bfloat16 al = __float2bfloat16(a - __bfloat162float(ah));
    __nv_bfloat16 bl = __float2bfloat16(b - __bfloat162float(bh));
    hi = (uint32_t)__bfloat16_as_ushort(ah) | ((uint32_t)__bfloat16_as_ushort(bh) << 16);
    lo = (uint32_t)__bfloat16_as_ushort(al) | ((uint32_t)__bfloat16_as_ushort(bl) << 16);
}

// pack two floats to bf16x2 (a -> low, b -> high), round-to-nearest
__device__ __forceinline__ uint32_t pack_bf16x2(float a, float b) {
    uint32_t r;
    asm("cvt.rn.bf16x2.f32 %0, %1, %2;" : "=r"(r) : "f"(b), "f"(a));
    return r;
}

__device__ __forceinline__ float fexp2(float x) {
    float y;
    asm("ex2.approx.f32 %0, %1;" : "=f"(y) : "f"(x));
    return y;
}

__device__ __forceinline__ void mma16816(float c[4], const uint32_t a[4],
                                         uint32_t b0, uint32_t b1) {
    asm volatile(
        "mma.sync.aligned.m16n8k16.row.col.f32.bf16.bf16.f32 "
        "{%0,%1,%2,%3},{%4,%5,%6,%7},{%8,%9},{%0,%1,%2,%3};\n"
        : "+f"(c[0]), "+f"(c[1]), "+f"(c[2]), "+f"(c[3])
        : "r"(a[0]), "r"(a[1]), "r"(a[2]), "r"(a[3]), "r"(b0), "r"(b1));
}

__device__ __forceinline__ void ldsm4(uint32_t r[4], uint32_t addr) {
    asm volatile("ldmatrix.sync.aligned.m8n8.x4.shared.b16 {%0,%1,%2,%3}, [%4];\n"
                 : "=r"(r[0]), "=r"(r[1]), "=r"(r[2]), "=r"(r[3]) : "r"(addr));
}

__device__ __forceinline__ void cpa(uint32_t saddr, const void* g) {
    asm volatile("cp.async.cg.shared.global [%0], [%1], 16;\n" :: "r"(saddr), "l"(g) : "memory");
}
#define CPCOMMIT() asm volatile("cp.async.commit_group;\n" ::: "memory")
#define CPWAIT1()  asm volatile("cp.async.wait_group 1;\n" ::: "memory")

// cvt: x pairs AND (x+pos) pairs in one pass
__global__ void cvt_x_kernel(const float* __restrict__ x, const float* __restrict__ pe) {
    int i = blockIdx.x * blockDim.x + threadIdx.x;
    if (i < MTOK * 512) {
        float2 v = ((const float2*)x)[i];
        split_pack(v.x, v.y, g_Xh[i], g_Xl[i]);
        int m = i >> 9, c = i & 511;
        int s = m & (SEQ - 1);
        float2 p = ((const float2*)pe)[s * 512 + c];
        split_pack(v.x + p.x, v.y + p.y, g_XPh[i], g_XPl[i]);
    }
}

__global__ void cvt_w_kernel(const float* __restrict__ Wqkv, const float* __restrict__ Wo) {
    int i = blockIdx.x * blockDim.x + threadIdx.x;
    const int N1 = 3 * HIDDEN * 512, N2 = HIDDEN * 512;
    if (i < N1) {
        int n = i % (3 * HIDDEN), kp = i / (3 * HIDDEN);
        split_pack(Wqkv[(size_t)(2 * kp) * 3072 + n], Wqkv[(size_t)(2 * kp + 1) * 3072 + n],
                   g_WTh[(size_t)n * 512 + kp], g_WTl[(size_t)n * 512 + kp]);
    } else if (i < N1 + N2) {
        int j = i - N1;
        int n = j % HIDDEN, kp = j / HIDDEN;
        split_pack(Wo[(size_t)(2 * kp) * HIDDEN + n], Wo[(size_t)(2 * kp + 1) * HIDDEN + n],
                   g_WoTh[(size_t)n * 512 + kp], g_WoTl[(size_t)n * 512 + kp]);
    }
}

// ---------------- GEMM: 128x128 tile, K-step 32 floats, cp.async 2-stage ----
extern __shared__ __align__(16) uint32_t dynsm[];

#define GEMM_PROLOG()                                                          \
    const int tid = threadIdx.x, lane = tid & 31, wid = tid >> 5;              \
    const int g = lane >> 2, tig = lane & 3;                                   \
    const int wm = wid >> 2, wn = wid & 3;                                     \
    const int m0 = blockIdx.y * 128, n0 = blockIdx.x * 128;                    \
    const uint32_t sbase = (uint32_t)__cvta_generic_to_shared(dynsm);          \
    const int row = tid >> 2, cc = (tid & 3) * 4;                              \
    const uint32_t dA0 = (uint32_t)(row * 20 + cc) * 4, dA1 = dA0 + 5120;      \
    const uint32_t foB = (uint32_t)(((lane & 7) + 8 * ((lane >> 3) & 1)) * 20  \
                                    + 4 * (lane >> 4)) * 4;                    \
    const uint32_t aB = (uint32_t)wm * 5120 + foB;                             \
    const uint32_t bB = (uint32_t)wn * 2560 + foB;                             \
    float acc[4][4][4];                                                        \
    for (int a_ = 0; a_ < 4; a_++)                                             \
        for (int b_ = 0; b_ < 4; b_++)                                         \
            for (int c_ = 0; c_ < 4; c_++) acc[a_][b_][c_] = 0.f;

#define GEMM_COMPUTE(bo)                                                       \
    _Pragma("unroll")                                                          \
    for (int ks = 0; ks < 2; ks++) {                                           \
        uint32_t ah[4][4], al[4][4], t0[4], t1[4], u0[4], u1[4];               \
        _Pragma("unroll")                                                      \
        for (int mi = 0; mi < 4; mi++) {                                       \
            ldsm4(ah[mi], sbase + (bo) + aB + mi * 1280 + ks * 32);            \
            ldsm4(al[mi], sbase + (bo) + 10240 + aB + mi * 1280 + ks * 32);    \
        }                                                                      \
        ldsm4(t0, sbase + (bo) + 20480 + bB + ks * 32);                        \
        ldsm4(t1, sbase + (bo) + 20480 + bB + 1280 + ks * 32);                 \
        ldsm4(u0, sbase + (bo) + 30720 + bB + ks * 32);                        \
        ldsm4(u1, sbase + (bo) + 30720 + bB + 1280 + ks * 32);                 \
        _Pragma("unroll")                                                      \
        for (int mi = 0; mi < 4; mi++) {                                       \
            mma16816(acc[mi][0], ah[mi], t0[0], t0[2]);                        \
            mma16816(acc[mi][1], ah[mi], t0[1], t0[3]);                        \
            mma16816(acc[mi][2], ah[mi], t1[0], t1[2]);                        \
            mma16816(acc[mi][3], ah[mi], t1[1], t1[3]);                        \
        }                                                                      \
        _Pragma("unroll")                                                      \
        for (int mi = 0; mi < 4; mi++) {                                       \
            mma16816(acc[mi][0], al[mi], t0[0], t0[2]);                        \
            mma16816(acc[mi][1], al[mi], t0[1], t0[3]);                        \
            mma16816(acc[mi][2], al[mi], t1[0], t1[2]);                        \
            mma16816(acc[mi][3], al[mi], t1[1], t1[3]);                        \
        }                                                                      \
        _Pragma("unroll")                                                      \
        for (int mi = 0; mi < 4; mi++) {                                       \
            mma16816(acc[mi][0], ah[mi], u0[0], u0[2]);                        \
            mma16816(acc[mi][1], ah[mi], u0[1], u0[3]);                        \
            mma16816(acc[mi][2], ah[mi], u1[0], u1[2]);                        \
            mma16816(acc[mi][3], ah[mi], u1[1], u1[3]);                        \
        }                                                                      \
    }

#define MAINLOOP_PIPE(STAGE)                                                   \
    STAGE(0, 0); CPCOMMIT();                                                   \
    for (int kt = 0; kt < 32; kt++) {                                          \
        if (kt + 1 < 32) { STAGE((kt + 1), ((kt + 1) & 1)); }                  \
        CPCOMMIT();                                                            \
        CPWAIT1(); __syncthreads();                                            \
        GEMM_COMPUTE((uint32_t)(kt & 1) * 40960u);                             \
        __syncthreads();                                                       \
    }

#define STAGE_STD(kt, b)                                                       \
    { uint32_t sb = sbase + (uint32_t)(b) * 40960u;                            \
      int off = (kt) * 16;                                                     \
      cpa(sb + dA0,          pAh0 + off);                                      \
      cpa(sb + dA1,          pAh1 + off);                                      \
      cpa(sb + 10240 + dA0,  pAl0 + off);                                      \
      cpa(sb + 10240 + dA1,  pAl1 + off);                                      \
      cpa(sb + 20480 + dA0,  pBh0 + off);                                      \
      cpa(sb + 20480 + dA1,  pBh1 + off);                                      \
      cpa(sb + 30720 + dA0,  pBl0 + off);                                      \
      cpa(sb + 30720 + dA1,  pBl1 + off); }

__global__ __launch_bounds__(256, 2) void qkv_gemm() {
    GEMM_PROLOG();
    const int reg = n0 >> 10;   // 0=Q 1=K 2=V, uniform per block
    const uint32_t* baseAh = (reg < 2) ? g_XPh : g_Xh;
    const uint32_t* baseAl = (reg < 2) ? g_XPl : g_Xl;
    const uint32_t* pAh0 = baseAh + (size_t)(m0 + row) * 512 + cc;
    const uint32_t* pAh1 = baseAh + (size_t)(m0 + row + 64) * 512 + cc;
    const uint32_t* pAl0 = baseAl + (size_t)(m0 + row) * 512 + cc;
    const uint32_t* pAl1 = baseAl + (size_t)(m0 + row + 64) * 512 + cc;
    const uint32_t* pBh0 = g_WTh + (size_t)(n0 + row) * 512 + cc;
    const uint32_t* pBh1 = g_WTh + (size_t)(n0 + row + 64) * 512 + cc;
    const uint32_t* pBl0 = g_WTl + (size_t)(n0 + row) * 512 + cc;
    const uint32_t* pBl1 = g_WTl + (size_t)(n0 + row + 64) * 512 + cc;
    MAINLOOP_PIPE(STAGE_STD);

#pragma unroll
    for (int mi = 0; mi < 4; mi++) {
#pragma unroll
        for (int nj = 0; nj < 4; nj++) {
            int m = m0 + wm * 64 + mi * 16 + g;
            int nn = n0 + wn * 32 + nj * 8 + 2 * tig;
            int bb = m >> 11, ss = m & 2047;
            float c0 = acc[mi][nj][0], c1 = acc[mi][nj][1];
            float c2 = acc[mi][nj][2], c3 = acc[mi][nj][3];
            if (reg < 2) {
                if (reg == 0) { c0 *= QSCALE; c1 *= QSCALE; c2 *= QSCALE; c3 *= QSCALE; }
                int head = (nn >> 6) & 15, hp = (nn & 63) >> 1;
                size_t bn = (size_t)bb * 16 + head;
                size_t i0 = (bn * SEQ + ss) * 32 + hp;
                size_t i1 = (bn * SEQ + ss + 8) * 32 + hp;
                uint32_t h01, l01, h23, l23;
                split_pack(c0, c1, h01, l01);
                split_pack(c2, c3, h23, l23);
                if (reg == 0) { g_Qh[i0] = h01; g_Ql[i0] = l01; g_Qh[i1] = h23; g_Ql[i1] = l23; }
                else          { g_Kh[i0] = h01; g_Kl[i0] = l01; g_Kh[i1] = h23; g_Kl[i1] = l23; }
            } else {
                float o0 = __shfl_xor_sync(0xffffffffu, c0, 4);
                float o1 = __shfl_xor_sync(0xffffffffu, c1, 4);
                float o2 = __shfl_xor_sync(0xffffffffu, c2, 4);
                float o3 = __shfl_xor_sync(0xffffffffu, c3, 4);
                if ((g & 1) == 0) {
                    int head = (nn >> 6) & 15;
                    size_t bn = (size_t)bb * 16 + head;
                    int h0 = nn & 63;
                    int sp0 = ss >> 1;
                    uint32_t hi, lo;
                    size_t b0 = (bn * HEADD + h0) * 1024;
                    size_t b1 = (bn * HEADD + h0 + 1) * 1024;
                    split_pack(c0, o0, hi, lo); g_VTh[b0 + sp0] = hi;     g_VTl[b0 + sp0] = lo;
                    split_pack(c1, o1, hi, lo); g_VTh[b1 + sp0] = hi;     g_VTl[b1 + sp0] = lo;
                    split_pack(c2, o2, hi, lo); g_VTh[b0 + sp0 + 4] = hi; g_VTl[b0 + sp0 + 4] = lo;
                    split_pack(c3, o3, hi, lo); g_VTh[b1 + sp0 + 4] = hi; g_VTl[b1 + sp0 + 4] = lo;
                }
            }
        }
    }
}

#define STAGE_OUT(kt, b)                                                       \
    { uint32_t sb = sbase + (uint32_t)(b) * 40960u;                            \
      int head = (kt) >> 1;                                                    \
      int wv = ((kt) & 1) * 16 + cc;                                           \
      const uint32_t* a0h = g_Oh + baseO + (size_t)head * (SEQ * 32) + wv;     \
      const uint32_t* a0l = g_Ol + baseO + (size_t)head * (SEQ * 32) + wv;     \
      cpa(sb + dA0,          a0h);                                             \
      cpa(sb + dA1,          a0h + 64 * 32);                                   \
      cpa(sb + 10240 + dA0,  a0l);                                             \
      cpa(sb + 10240 + dA1,  a0l + 64 * 32);                                   \
      int off = (kt) * 16;                                                     \
      cpa(sb + 20480 + dA0,  pBh0 + off);                                      \
      cpa(sb + 20480 + dA1,  pBh1 + off);                                      \
      cpa(sb + 30720 + dA0,  pBl0 + off);                                      \
      cpa(sb + 30720 + dA1,  pBl1 + off); }

__global__ __launch_bounds__(256, 2) void out_gemm(float* __restrict__ out) {
    GEMM_PROLOG();
    const int arow = m0 + row;
    const int bb = arow >> 11, ss = arow & 2047;
    const size_t baseO = ((size_t)bb * 16 * SEQ + ss) * 32;
    const uint32_t* pBh0 = g_WoTh + (size_t)(n0 + row) * 512 + cc;
    const uint32_t* pBh1 = g_WoTh + (size_t)(n0 + row + 64) * 512 + cc;
    const uint32_t* pBl0 = g_WoTl + (size_t)(n0 + row) * 512 + cc;
    const uint32_t* pBl1 = g_WoTl + (size_t)(n0 + row + 64) * 512 + cc;
    MAINLOOP_PIPE(STAGE_OUT);
#pragma unroll
    for (int mi = 0; mi < 4; mi++)
#pragma unroll
        for (int nj = 0; nj < 4; nj++) {
            int m = m0 + wm * 64 + mi * 16 + g;
            int nn = n0 + wn * 32 + nj * 8 + 2 * tig;
            *(float2*)(out + (size_t)m * HIDDEN + nn) = make_float2(acc[mi][nj][0], acc[mi][nj][1]);
            *(float2*)(out + (size_t)(m + 8) * HIDDEN + nn) = make_float2(acc[mi][nj][2], acc[mi][nj][3]);
        }
}

// ---------------- flash attention: 128-query blocks, 8 warps --------------
// dyn smem (u32): Kh[64][44]@0, Kl@2816, Vh@5632, Vl@8448, Ph[128][44]@11264
#define ATTN_SMEM 67584

__global__ __launch_bounds__(256, 2) void attn_kernel() {
    uint32_t* Kh = dynsm;
    uint32_t* Kl = dynsm + 2816;
    uint32_t* Vh = dynsm + 5632;
    uint32_t* Vl = dynsm + 8448;
    uint32_t* Ph = dynsm + 11264;

    const int tid = threadIdx.x, lane = tid & 31, w = tid >> 5;
    const int g = lane >> 2, tig = lane & 3;
    const int bn = blockIdx.x, qb = blockIdx.y;

    const uint32_t sbase = (uint32_t)__cvta_generic_to_shared(dynsm);
    const uint32_t sKh = sbase,          sKl = sbase + 11264;
    const uint32_t sVh = sbase + 22528,  sVl = sbase + 33792;
    const uint32_t sPh = sbase + 45056;
    const uint32_t foA = (uint32_t)(((lane & 7) + 8 * ((lane >> 3) & 1)) * 176 + 16 * (lane >> 4));

    const int qr = qb * 128 + 16 * w + g;
    const uint32_t* qbh = g_Qh + ((size_t)bn * SEQ + qr) * 32 + tig;
    const uint32_t* qbl = g_Ql + ((size_t)bn * SEQ + qr) * 32 + tig;
    uint32_t qah[4][4], qal[4][4];
#pragma unroll
    for (int ks = 0; ks < 4; ks++) {
        qah[ks][0] = qbh[ks * 8];     qah[ks][1] = qbh[256 + ks * 8];
        qah[ks][2] = qbh[ks * 8 + 4]; qah[ks][3] = qbh[256 + ks * 8 + 4];
        qal[ks][0] = qbl[ks * 8];     qal[ks][1] = qbl[256 + ks * 8];
        qal[ks][2] = qbl[ks * 8 + 4]; qal[ks][3] = qbl[256 + ks * 8 + 4];
    }

    float o[8][4];
#pragma unroll
    for (int nt = 0; nt < 8; nt++)
#pragma unroll
        for (int c = 0; c < 4; c++) o[nt][c] = 0.f;
    float mrun0 = -1e30f, mrun1 = -1e30f, lrun0 = 0.f, lrun1 = 0.f;

    const int lrow = tid >> 2, cb = (tid & 3) * 8;
    const int sidx = lrow * 44 + cb;
    const uint32_t* kgh = g_Kh + ((size_t)bn * SEQ + lrow) * 32 + cb;
    const uint32_t* kgl = g_Kl + ((size_t)bn * SEQ + lrow) * 32 + cb;
    const uint32_t* vgh = g_VTh + ((size_t)bn * HEADD + lrow) * 1024 + cb;
    const uint32_t* vgl = g_VTl + ((size_t)bn * HEADD + lrow) * 1024 + cb;

    const int ntiles = 2 * qb + 2;
    for (int kt = 0; kt < ntiles; kt++) {
        const int kbase = kt * 64;
        __syncthreads();
        {
            size_t ko = (size_t)kbase * 32, vo = (size_t)kt * 32;
            *(uint4*)&Kh[sidx]     = *(const uint4*)(kgh + ko);
            *(uint4*)&Kh[sidx + 4] = *(const uint4*)(kgh + ko + 4);
            *(uint4*)&Kl[sidx]     = *(const uint4*)(kgl + ko);
            *(uint4*)&Kl[sidx + 4] = *(const uint4*)(kgl + ko + 4);
            *(uint4*)&Vh[sidx]     = *(const uint4*)(vgh + vo);
            *(uint4*)&Vh[sidx + 4] = *(const uint4*)(vgh + vo + 4);
            *(uint4*)&Vl[sidx]     = *(const uint4*)(vgl + vo);
            *(uint4*)&Vl[sidx + 4] = *(const uint4*)(vgl + vo + 4);
        }
        __syncthreads();

        // S = Qs @ K^T (3-term bf16x3), S already in log2e units
        float sacc[8][4];
#pragma unroll
        for (int nt = 0; nt < 8; nt++)
#pragma unroll
            for (int c = 0; c < 4; c++) sacc[nt][c] = 0.f;
#pragma unroll
        for (int ks = 0; ks < 4; ks++) {
#pragma unroll
            for (int mp = 0; mp < 4; mp += 2) {
                uint32_t tka[4], uka[4], tkb[4], ukb[4];
                ldsm4(tka, sKh + mp * 2816 + ks * 32 + foA);
                ldsm4(uka, sKl + mp * 2816 + ks * 32 + foA);
                ldsm4(tkb, sKh + (mp + 1) * 2816 + ks * 32 + foA);
                ldsm4(ukb, sKl + (mp + 1) * 2816 + ks * 32 + foA);
                mma16816(sacc[2 * mp],     qah[ks], tka[0], tka[2]);
                mma16816(sacc[2 * mp + 1], qah[ks], tka[1], tka[3]);
                mma16816(sacc[2 * mp + 2], qah[ks], tkb[0], tkb[2]);
                mma16816(sacc[2 * mp + 3], qah[ks], tkb[1], tkb[3]);
                mma16816(sacc[2 * mp],     qal[ks], tka[0], tka[2]);
                mma16816(sacc[2 * mp + 1], qal[ks], tka[1], tka[3]);
                mma16816(sacc[2 * mp + 2], qal[ks], tkb[0], tkb[2]);
                mma16816(sacc[2 * mp + 3], qal[ks], tkb[1], tkb[3]);
                mma16816(sacc[2 * mp],     qah[ks], uka[0], uka[2]);
                mma16816(sacc[2 * mp + 1], qah[ks], uka[1], uka[3]);
                mma16816(sacc[2 * mp + 2], qah[ks], ukb[0], ukb[2]);
                mma16816(sacc[2 * mp + 3], qah[ks], ukb[1], ukb[3]);
            }
        }

        if (kbase + 63 > qr) {
#pragma unroll
            for (int nt = 0; nt < 8; nt++) {
                int kg = kbase + nt * 8 + 2 * tig;
                if (kg > qr)         sacc[nt][0] = -1e30f;
                if (kg + 1 > qr)     sacc[nt][1] = -1e30f;
                if (kg > qr + 8)     sacc[nt][2] = -1e30f;
                if (kg + 1 > qr + 8) sacc[nt][3] = -1e30f;
            }
        }

        // online softmax in exp2 domain
        float ml0 = -1e30f, ml1 = -1e30f;
#pragma unroll
        for (int nt = 0; nt < 8; nt++) {
            ml0 = fmaxf(ml0, fmaxf(sacc[nt][0], sacc[nt][1]));
            ml1 = fmaxf(ml1, fmaxf(sacc[nt][2], sacc[nt][3]));
        }
        ml0 = fmaxf(ml0, __shfl_xor_sync(0xffffffffu, ml0, 1));
        ml0 = fmaxf(ml0, __shfl_xor_sync(0xffffffffu, ml0, 2));
        ml1 = fmaxf(ml1, __shfl_xor_sync(0xffffffffu, ml1, 1));
        ml1 = fmaxf(ml1, __shfl_xor_sync(0xffffffffu, ml1, 2));
        float mn0 = fmaxf(mrun0, ml0), mn1 = fmaxf(mrun1, ml1);
        float scl0 = fexp2(mrun0 - mn0), scl1 = fexp2(mrun1 - mn1);
        mrun0 = mn0; mrun1 = mn1;
        float ls0 = 0.f, ls1 = 0.f;
#pragma unroll
        for (int nt = 0; nt < 8; nt++) {
            float p0 = fexp2(sacc[nt][0] - mn0);
            float p1 = fexp2(sacc[nt][1] - mn0);
            float p2 = fexp2(sacc[nt][2] - mn1);
            float p3 = fexp2(sacc[nt][3] - mn1);
            ls0 += p0 + p1; ls1 += p2 + p3;
            sacc[nt][0] = p0; sacc[nt][1] = p1; sacc[nt][2] = p2; sacc[nt][3] = p3;
            o[nt][0] *= scl0; o[nt][1] *= scl0; o[nt][2] *= scl1; o[nt][3] *= scl1;
        }
        lrun0 = lrun0 * scl0 + ls0;
        lrun1 = lrun1 * scl1 + ls1;

        // P store: bf16 (hi only), rows warp-private
#pragma unroll
        for (int nt = 0; nt < 8; nt++) {
            Ph[(16 * w + g) * 44 + nt * 4 + tig]     = pack_bf16x2(sacc[nt][0], sacc[nt][1]);
            Ph[(16 * w + g + 8) * 44 + nt * 4 + tig] = pack_bf16x2(sacc[nt][2], sacc[nt][3]);
        }
        __syncwarp();

        // O += P @ V (2-term: ph*vh + ph*vl)
#pragma unroll
        for (int ks = 0; ks < 4; ks++) {
            uint32_t ph[4];
            ldsm4(ph, sPh + w * 2816 + ks * 32 + foA);
#pragma unroll
            for (int mp = 0; mp < 4; mp += 2) {
                uint32_t tva[4], uva[4], tvb[4], uvb[4];
                ldsm4(tva, sVh + mp * 2816 + ks * 32 + foA);
                ldsm4(uva, sVl + mp * 2816 + ks * 32 + foA);
                ldsm4(tvb, sVh + (mp + 1) * 2816 + ks * 32 + foA);
                ldsm4(uvb, sVl + (mp + 1) * 2816 + ks * 32 + foA);
                mma16816(o[2 * mp],     ph, tva[0], tva[2]);
                mma16816(o[2 * mp + 1], ph, tva[1], tva[3]);
                mma16816(o[2 * mp + 2], ph, tvb[0], tvb[2]);
                mma16816(o[2 * mp + 3], ph, tvb[1], tvb[3]);
                mma16816(o[2 * mp],     ph, uva[0], uva[2]);
                mma16816(o[2 * mp + 1], ph, uva[1], uva[3]);
                mma16816(o[2 * mp + 2], ph, uvb[0], uvb[2]);
                mma16816(o[2 * mp + 3], ph, uvb[1], uvb[3]);
            }
        }
    }

    lrun0 += __shfl_xor_sync(0xffffffffu, lrun0, 1);
    lrun0 += __shfl_xor_sync(0xffffffffu, lrun0, 2);
    lrun1 += __shfl_xor_sync(0xffffffffu, lrun1, 1);
    lrun1 += __shfl_xor_sync(0xffffffffu, lrun1, 2);
    float inv0 = 1.f / lrun0, inv1 = 1.f / lrun1;
    size_t ob0 = ((size_t)bn * SEQ + qr) * 32 + tig;
    size_t ob1 = ((size_t)bn * SEQ + qr + 8) * 32 + tig;
#pragma unroll
    for (int nt = 0; nt < 8; nt++) {
        uint32_t hi, lo;
        split_pack(o[nt][0] * inv0, o[nt][1] * inv0, hi, lo);
        g_Oh[ob0 + nt * 4] = hi;  g_Ol[ob0 + nt * 4] = lo;
        split_pack(o[nt][2] * inv1, o[nt][3] * inv1, hi, lo);
        g_Oh[ob1 + nt * 4] = hi;  g_Ol[ob1 + nt * 4] = lo;
    }
}

extern "C" void kernel_launch(void* const* d_in, const int* in_sizes, int n_in,
                              void* d_out, int out_size)
{
    const float* x    = (const float*)d_in[0];
    const float* pe   = (const float*)d_in[1];
    const float* Wqkv = (const float*)d_in[2];
    const float* Wo   = (const float*)d_in[3];
    float* out = (float*)d_out;

    const int SMEM_DYN = 2 * 40960;
    cudaFuncSetAttribute(qkv_gemm, cudaFuncAttributeMaxDynamicSharedMemorySize, SMEM_DYN);
    cudaFuncSetAttribute(out_gemm, cudaFuncAttributeMaxDynamicSharedMemorySize, SMEM_DYN);
    cudaFuncSetAttribute(attn_kernel, cudaFuncAttributeMaxDynamicSharedMemorySize, ATTN_SMEM);

    cvt_x_kernel<<<(MTOK * 512 + 255) / 256, 256>>>(x, pe);
    cvt_w_kernel<<<(4 * HIDDEN * 512 + 255) / 256, 256>>>(Wqkv, Wo);
    qkv_gemm<<<dim3(3 * HIDDEN / 128, MTOK / 128), 256, SMEM_DYN>>>();
    attn_kernel<<<dim3(BNH, SEQ / 128), 256, ATTN_SMEM>>>();
    out_gemm<<<dim3(HIDDEN / 128, MTOK / 128), 256, SMEM_DYN>>>(out);
}

// round 17
// speedup vs baseline: 1.1390x; 1.0672x over previous
#include <cuda_runtime.h>
#include <cuda_bf16.h>
#include <cstdint>
#include <math.h>

#define HIDDEN 1024
#define NHEADS 16
#define HEADD  64
#define BATCH  4
#define SEQ    2048
#define MTOK   (BATCH*SEQ)
#define BNH    (BATCH*NHEADS)

// Q scale folded with log2(e): 0.125 * 1.4426950408889634
#define QSCALE 0.18033688011112042f

// packed bf16 hi/lo pairs as u32
__device__ __align__(16) uint32_t g_Xh[MTOK*512],  g_Xl[MTOK*512];   // x
__device__ __align__(16) uint32_t g_XPh[MTOK*512], g_XPl[MTOK*512]; // x + pos
__device__ __align__(16) uint32_t g_WTh[3*HIDDEN*512], g_WTl[3*HIDDEN*512];
__device__ __align__(16) uint32_t g_WoTh[HIDDEN*512],  g_WoTl[HIDDEN*512];
__device__ __align__(16) uint32_t g_Qh[BNH*SEQ*32], g_Ql[BNH*SEQ*32];
__device__ __align__(16) uint32_t g_Kh[BNH*SEQ*32], g_Kl[BNH*SEQ*32];
__device__ __align__(16) uint32_t g_VT[BNH*HEADD*1024];   // V^T as fp16x2 (seq pairs)
__device__ __align__(16) uint32_t g_Oh[BNH*SEQ*32], g_Ol[BNH*SEQ*32];

__device__ __forceinline__ void split_pack(float a, float b, uint32_t& hi, uint32_t& lo) {
    __nv_bfloat16 ah = __float2bfloat16(a);
    __nv_bfloat16 bh = __float2bfloat16(b);
    __nv_bfloat16 al = __float2bfloat16(a - __bfloat162float(ah));
    __nv_bfloat16 bl = __float2bfloat16(b - __bfloat162float(bh));
    hi = (uint32_t)__bfloat16_as_ushort(ah) | ((uint32_t)__bfloat16_as_ushort(bh) << 16);
    lo = (uint32_t)__bfloat16_as_ushort(al) | ((uint32_t)__bfloat16_as_ushort(bl) << 16);
}

// pack two floats to fp16x2 (a -> low half, b -> high half)
__device__ __forceinline__ uint32_t pack_f16x2(float a, float b) {
    uint32_t r;
    asm("cvt.rn.f16x2.f32 %0, %1, %2;" : "=r"(r) : "f"(b), "f"(a));
    return r;
}

__device__ __forceinline__ float fexp2(float x) {
    float y;
    asm("ex2.approx.f32 %0, %1;" : "=f"(y) : "f"(x));
    return y;
}

__device__ __forceinline__ void mma16816(float c[4], const uint32_t a[4],
                                         uint32_t b0, uint32_t b1) {
    asm volatile(
        "mma.sync.aligned.m16n8k16.row.col.f32.bf16.bf16.f32 "
        "{%0,%1,%2,%3},{%4,%5,%6,%7},{%8,%9},{%0,%1,%2,%3};\n"
        : "+f"(c[0]), "+f"(c[1]), "+f"(c[2]), "+f"(c[3])
        : "r"(a[0]), "r"(a[1]), "r"(a[2]), "r"(a[3]), "r"(b0), "r"(b1));
}

__device__ __forceinline__ void mma16816f(float c[4], const uint32_t a[4],
                                          uint32_t b0, uint32_t b1) {
    asm volatile(
        "mma.sync.aligned.m16n8k16.row.col.f32.f16.f16.f32 "
        "{%0,%1,%2,%3},{%4,%5,%6,%7},{%8,%9},{%0,%1,%2,%3};\n"
        : "+f"(c[0]), "+f"(c[1]), "+f"(c[2]), "+f"(c[3])
        : "r"(a[0]), "r"(a[1]), "r"(a[2]), "r"(a[3]), "r"(b0), "r"(b1));
}

__device__ __forceinline__ void ldsm4(uint32_t r[4], uint32_t addr) {
    asm volatile("ldmatrix.sync.aligned.m8n8.x4.shared.b16 {%0,%1,%2,%3}, [%4];\n"
                 : "=r"(r[0]), "=r"(r[1]), "=r"(r[2]), "=r"(r[3]) : "r"(addr));
}

__device__ __forceinline__ void cpa(uint32_t saddr, const void* g) {
    asm volatile("cp.async.cg.shared.global [%0], [%1], 16;\n" :: "r"(saddr), "l"(g) : "memory");
}
#define CPCOMMIT() asm volatile("cp.async.commit_group;\n" ::: "memory")
#define CPWAIT1()  asm volatile("cp.async.wait_group 1;\n" ::: "memory")

// cvt: x pairs AND (x+pos) pairs in one pass
__global__ void cvt_x_kernel(const float* __restrict__ x, const float* __restrict__ pe) {
    int i = blockIdx.x * blockDim.x + threadIdx.x;
    if (i < MTOK * 512) {
        float2 v = ((const float2*)x)[i];
        split_pack(v.x, v.y, g_Xh[i], g_Xl[i]);
        int m = i >> 9, c = i & 511;
        int s = m & (SEQ - 1);
        float2 p = ((const float2*)pe)[s * 512 + c];
        split_pack(v.x + p.x, v.y + p.y, g_XPh[i], g_XPl[i]);
    }
}

__global__ void cvt_w_kernel(const float* __restrict__ Wqkv, const float* __restrict__ Wo) {
    int i = blockIdx.x * blockDim.x + threadIdx.x;
    const int N1 = 3 * HIDDEN * 512, N2 = HIDDEN * 512;
    if (i < N1) {
        int n = i % (3 * HIDDEN), kp = i / (3 * HIDDEN);
        split_pack(Wqkv[(size_t)(2 * kp) * 3072 + n], Wqkv[(size_t)(2 * kp + 1) * 3072 + n],
                   g_WTh[(size_t)n * 512 + kp], g_WTl[(size_t)n * 512 + kp]);
    } else if (i < N1 + N2) {
        int j = i - N1;
        int n = j % HIDDEN, kp = j / HIDDEN;
        split_pack(Wo[(size_t)(2 * kp) * HIDDEN + n], Wo[(size_t)(2 * kp + 1) * HIDDEN + n],
                   g_WoTh[(size_t)n * 512 + kp], g_WoTl[(size_t)n * 512 + kp]);
    }
}

// ---------------- GEMM: 128x128 tile, K-step 32 floats, cp.async 2-stage ----
extern __shared__ __align__(16) uint32_t dynsm[];

#define GEMM_PROLOG()                                                          \
    const int tid = threadIdx.x, lane = tid & 31, wid = tid >> 5;              \
    const int g = lane >> 2, tig = lane & 3;                                   \
    const int wm = wid >> 2, wn = wid & 3;                                     \
    const int m0 = blockIdx.y * 128, n0 = blockIdx.x * 128;                    \
    const uint32_t sbase = (uint32_t)__cvta_generic_to_shared(dynsm);          \
    const int row = tid >> 2, cc = (tid & 3) * 4;                              \
    const uint32_t dA0 = (uint32_t)(row * 20 + cc) * 4, dA1 = dA0 + 5120;      \
    const uint32_t foB = (uint32_t)(((lane & 7) + 8 * ((lane >> 3) & 1)) * 20  \
                                    + 4 * (lane >> 4)) * 4;                    \
    const uint32_t aB = (uint32_t)wm * 5120 + foB;                             \
    const uint32_t bB = (uint32_t)wn * 2560 + foB;                             \
    float acc[4][4][4];                                                        \
    for (int a_ = 0; a_ < 4; a_++)                                             \
        for (int b_ = 0; b_ < 4; b_++)                                         \
            for (int c_ = 0; c_ < 4; c_++) acc[a_][b_][c_] = 0.f;

#define GEMM_COMPUTE(bo)                                                       \
    _Pragma("unroll")                                                          \
    for (int ks = 0; ks < 2; ks++) {                                           \
        uint32_t ah[4][4], al[4][4], t0[4], t1[4], u0[4], u1[4];               \
        _Pragma("unroll")                                                      \
        for (int mi = 0; mi < 4; mi++) {                                       \
            ldsm4(ah[mi], sbase + (bo) + aB + mi * 1280 + ks * 32);            \
            ldsm4(al[mi], sbase + (bo) + 10240 + aB + mi * 1280 + ks * 32);    \
        }                                                                      \
        ldsm4(t0, sbase + (bo) + 20480 + bB + ks * 32);                        \
        ldsm4(t1, sbase + (bo) + 20480 + bB + 1280 + ks * 32);                 \
        ldsm4(u0, sbase + (bo) + 30720 + bB + ks * 32);                        \
        ldsm4(u1, sbase + (bo) + 30720 + bB + 1280 + ks * 32);                 \
        _Pragma("unroll")                                                      \
        for (int mi = 0; mi < 4; mi++) {                                       \
            mma16816(acc[mi][0], ah[mi], t0[0], t0[2]);                        \
            mma16816(acc[mi][1], ah[mi], t0[1], t0[3]);                        \
            mma16816(acc[mi][2], ah[mi], t1[0], t1[2]);                        \
            mma16816(acc[mi][3], ah[mi], t1[1], t1[3]);                        \
        }                                                                      \
        _Pragma("unroll")                                                      \
        for (int mi = 0; mi < 4; mi++) {                                       \
            mma16816(acc[mi][0], al[mi], t0[0], t0[2]);                        \
            mma16816(acc[mi][1], al[mi], t0[1], t0[3]);                        \
            mma16816(acc[mi][2], al[mi], t1[0], t1[2]);                        \
            mma16816(acc[mi][3], al[mi], t1[1], t1[3]);                        \
        }                                                                      \
        _Pragma("unroll")                                                      \
        for (int mi = 0; mi < 4; mi++) {                                       \
            mma16816(acc[mi][0], ah[mi], u0[0], u0[2]);                        \
            mma16816(acc[mi][1], ah[mi], u0[1], u0[3]);                        \
            mma16816(acc[mi][2], ah[mi], u1[0], u1[2]);                        \
            mma16816(acc[mi][3], ah[mi], u1[1], u1[3]);                        \
        }                                                                      \
    }

#define MAINLOOP_PIPE(STAGE)                                                   \
    STAGE(0, 0); CPCOMMIT();                                                   \
    for (int kt = 0; kt < 32; kt++) {                                          \
        if (kt + 1 < 32) { STAGE((kt + 1), ((kt + 1) & 1)); }                  \
        CPCOMMIT();                                                            \
        CPWAIT1(); __syncthreads();                                            \
        GEMM_COMPUTE((uint32_t)(kt & 1) * 40960u);                             \
        __syncthreads();                                                       \
    }

#define STAGE_STD(kt, b)                                                       \
    { uint32_t sb = sbase + (uint32_t)(b) * 40960u;                            \
      int off = (kt) * 16;                                                     \
      cpa(sb + dA0,          pAh0 + off);                                      \
      cpa(sb + dA1,          pAh1 + off);                                      \
      cpa(sb + 10240 + dA0,  pAl0 + off);                                      \
      cpa(sb + 10240 + dA1,  pAl1 + off);                                      \
      cpa(sb + 20480 + dA0,  pBh0 + off);                                      \
      cpa(sb + 20480 + dA1,  pBh1 + off);                                      \
      cpa(sb + 30720 + dA0,  pBl0 + off);                                      \
      cpa(sb + 30720 + dA1,  pBl1 + off); }

__global__ __launch_bounds__(256, 2) void qkv_gemm() {
    GEMM_PROLOG();
    const int reg = n0 >> 10;   // 0=Q 1=K 2=V, uniform per block
    const uint32_t* baseAh = (reg < 2) ? g_XPh : g_Xh;
    const uint32_t* baseAl = (reg < 2) ? g_XPl : g_Xl;
    const uint32_t* pAh0 = baseAh + (size_t)(m0 + row) * 512 + cc;
    const uint32_t* pAh1 = baseAh + (size_t)(m0 + row + 64) * 512 + cc;
    const uint32_t* pAl0 = baseAl + (size_t)(m0 + row) * 512 + cc;
    const uint32_t* pAl1 = baseAl + (size_t)(m0 + row + 64) * 512 + cc;
    const uint32_t* pBh0 = g_WTh + (size_t)(n0 + row) * 512 + cc;
    const uint32_t* pBh1 = g_WTh + (size_t)(n0 + row + 64) * 512 + cc;
    const uint32_t* pBl0 = g_WTl + (size_t)(n0 + row) * 512 + cc;
    const uint32_t* pBl1 = g_WTl + (size_t)(n0 + row + 64) * 512 + cc;
    MAINLOOP_PIPE(STAGE_STD);

#pragma unroll
    for (int mi = 0; mi < 4; mi++) {
#pragma unroll
        for (int nj = 0; nj < 4; nj++) {
            int m = m0 + wm * 64 + mi * 16 + g;
            int nn = n0 + wn * 32 + nj * 8 + 2 * tig;
            int bb = m >> 11, ss = m & 2047;
            float c0 = acc[mi][nj][0], c1 = acc[mi][nj][1];
            float c2 = acc[mi][nj][2], c3 = acc[mi][nj][3];
            if (reg < 2) {
                if (reg == 0) { c0 *= QSCALE; c1 *= QSCALE; c2 *= QSCALE; c3 *= QSCALE; }
                int head = (nn >> 6) & 15, hp = (nn & 63) >> 1;
                size_t bn = (size_t)bb * 16 + head;
                size_t i0 = (bn * SEQ + ss) * 32 + hp;
                size_t i1 = (bn * SEQ + ss + 8) * 32 + hp;
                uint32_t h01, l01, h23, l23;
                split_pack(c0, c1, h01, l01);
                split_pack(c2, c3, h23, l23);
                if (reg == 0) { g_Qh[i0] = h01; g_Ql[i0] = l01; g_Qh[i1] = h23; g_Ql[i1] = l23; }
                else          { g_Kh[i0] = h01; g_Kl[i0] = l01; g_Kh[i1] = h23; g_Kl[i1] = l23; }
            } else {
                float o0 = __shfl_xor_sync(0xffffffffu, c0, 4);
                float o1 = __shfl_xor_sync(0xffffffffu, c1, 4);
                float o2 = __shfl_xor_sync(0xffffffffu, c2, 4);
                float o3 = __shfl_xor_sync(0xffffffffu, c3, 4);
                if ((g & 1) == 0) {
                    int head = (nn >> 6) & 15;
                    size_t bn = (size_t)bb * 16 + head;
                    int h0 = nn & 63;
                    int sp0 = ss >> 1;
                    size_t b0 = (bn * HEADD + h0) * 1024;
                    size_t b1 = (bn * HEADD + h0 + 1) * 1024;
                    g_VT[b0 + sp0]     = pack_f16x2(c0, o0);
                    g_VT[b1 + sp0]     = pack_f16x2(c1, o1);
                    g_VT[b0 + sp0 + 4] = pack_f16x2(c2, o2);
                    g_VT[b1 + sp0 + 4] = pack_f16x2(c3, o3);
                }
            }
        }
    }
}

#define STAGE_OUT(kt, b)                                                       \
    { uint32_t sb = sbase + (uint32_t)(b) * 40960u;                            \
      int head = (kt) >> 1;                                                    \
      int wv = ((kt) & 1) * 16 + cc;                                           \
      const uint32_t* a0h = g_Oh + baseO + (size_t)head * (SEQ * 32) + wv;     \
      const uint32_t* a0l = g_Ol + baseO + (size_t)head * (SEQ * 32) + wv;     \
      cpa(sb + dA0,          a0h);                                             \
      cpa(sb + dA1,          a0h + 64 * 32);                                   \
      cpa(sb + 10240 + dA0,  a0l);                                             \
      cpa(sb + 10240 + dA1,  a0l + 64 * 32);                                   \
      int off = (kt) * 16;                                                     \
      cpa(sb + 20480 + dA0,  pBh0 + off);                                      \
      cpa(sb + 20480 + dA1,  pBh1 + off);                                      \
      cpa(sb + 30720 + dA0,  pBl0 + off);                                      \
      cpa(sb + 30720 + dA1,  pBl1 + off); }

__global__ __launch_bounds__(256, 2) void out_gemm(float* __restrict__ out) {
    GEMM_PROLOG();
    const int arow = m0 + row;
    const int bb = arow >> 11, ss = arow & 2047;
    const size_t baseO = ((size_t)bb * 16 * SEQ + ss) * 32;
    const uint32_t* pBh0 = g_WoTh + (size_t)(n0 + row) * 512 + cc;
    const uint32_t* pBh1 = g_WoTh + (size_t)(n0 + row + 64) * 512 + cc;
    const uint32_t* pBl0 = g_WoTl + (size_t)(n0 + row) * 512 + cc;
    const uint32_t* pBl1 = g_WoTl + (size_t)(n0 + row + 64) * 512 + cc;
    MAINLOOP_PIPE(STAGE_OUT);
#pragma unroll
    for (int mi = 0; mi < 4; mi++)
#pragma unroll
        for (int nj = 0; nj < 4; nj++) {
            int m = m0 + wm * 64 + mi * 16 + g;
            int nn = n0 + wn * 32 + nj * 8 + 2 * tig;
            *(float2*)(out + (size_t)m * HIDDEN + nn) = make_float2(acc[mi][nj][0], acc[mi][nj][1]);
            *(float2*)(out + (size_t)(m + 8) * HIDDEN + nn) = make_float2(acc[mi][nj][2], acc[mi][nj][3]);
        }
}

// ---------------- flash attention: 128-query blocks, 8 warps --------------
// dyn smem (u32): Kh[64][44]@0, Kl@2816, V@5632 (fp16x2), Ph[128][44]@8448 (fp16x2)
#define ATTN_SMEM 56320

__global__ __launch_bounds__(256, 2) void attn_kernel() {
    uint32_t* Kh = dynsm;
    uint32_t* Kl = dynsm + 2816;
    uint32_t* Vs = dynsm + 5632;
    uint32_t* Ph = dynsm + 8448;

    const int tid = threadIdx.x, lane = tid & 31, w = tid >> 5;
    const int g = lane >> 2, tig = lane & 3;
    const int bn = blockIdx.x, qb = blockIdx.y;

    const uint32_t sbase = (uint32_t)__cvta_generic_to_shared(dynsm);
    const uint32_t sKh = sbase,          sKl = sbase + 11264;
    const uint32_t sV  = sbase + 22528,  sPh = sbase + 33792;
    const uint32_t foA = (uint32_t)(((lane & 7) + 8 * ((lane >> 3) & 1)) * 176 + 16 * (lane >> 4));

    const int qr = qb * 128 + 16 * w + g;
    const uint32_t* qbh = g_Qh + ((size_t)bn * SEQ + qr) * 32 + tig;
    const uint32_t* qbl = g_Ql + ((size_t)bn * SEQ + qr) * 32 + tig;
    uint32_t qah[4][4], qal[4][4];
#pragma unroll
    for (int ks = 0; ks < 4; ks++) {
        qah[ks][0] = qbh[ks * 8];     qah[ks][1] = qbh[256 + ks * 8];
        qah[ks][2] = qbh[ks * 8 + 4]; qah[ks][3] = qbh[256 + ks * 8 + 4];
        qal[ks][0] = qbl[ks * 8];     qal[ks][1] = qbl[256 + ks * 8];
        qal[ks][2] = qbl[ks * 8 + 4]; qal[ks][3] = qbl[256 + ks * 8 + 4];
    }

    float o[8][4];
#pragma unroll
    for (int nt = 0; nt < 8; nt++)
#pragma unroll
        for (int c = 0; c < 4; c++) o[nt][c] = 0.f;
    float mrun0 = -1e30f, mrun1 = -1e30f, lrun0 = 0.f, lrun1 = 0.f;

    const int lrow = tid >> 2, cb = (tid & 3) * 8;
    const int sidx = lrow * 44 + cb;
    const uint32_t* kgh = g_Kh + ((size_t)bn * SEQ + lrow) * 32 + cb;
    const uint32_t* kgl = g_Kl + ((size_t)bn * SEQ + lrow) * 32 + cb;
    const uint32_t* vg  = g_VT + ((size_t)bn * HEADD + lrow) * 1024 + cb;

    const int ntiles = 2 * qb + 2;
    for (int kt = 0; kt < ntiles; kt++) {
        const int kbase = kt * 64;
        __syncthreads();
        {
            size_t ko = (size_t)kbase * 32, vo = (size_t)kt * 32;
            *(uint4*)&Kh[sidx]     = *(const uint4*)(kgh + ko);
            *(uint4*)&Kh[sidx + 4] = *(const uint4*)(kgh + ko + 4);
            *(uint4*)&Kl[sidx]     = *(const uint4*)(kgl + ko);
            *(uint4*)&Kl[sidx + 4] = *(const uint4*)(kgl + ko + 4);
            *(uint4*)&Vs[sidx]     = *(const uint4*)(vg + vo);
            *(uint4*)&Vs[sidx + 4] = *(const uint4*)(vg + vo + 4);
        }
        __syncthreads();

        // S = Qs @ K^T (3-term bf16x3), S already in log2e units
        float sacc[8][4];
#pragma unroll
        for (int nt = 0; nt < 8; nt++)
#pragma unroll
            for (int c = 0; c < 4; c++) sacc[nt][c] = 0.f;
#pragma unroll
        for (int ks = 0; ks < 4; ks++) {
#pragma unroll
            for (int mp = 0; mp < 4; mp += 2) {
                uint32_t tka[4], uka[4], tkb[4], ukb[4];
                ldsm4(tka, sKh + mp * 2816 + ks * 32 + foA);
                ldsm4(uka, sKl + mp * 2816 + ks * 32 + foA);
                ldsm4(tkb, sKh + (mp + 1) * 2816 + ks * 32 + foA);
                ldsm4(ukb, sKl + (mp + 1) * 2816 + ks * 32 + foA);
                mma16816(sacc[2 * mp],     qah[ks], tka[0], tka[2]);
                mma16816(sacc[2 * mp + 1], qah[ks], tka[1], tka[3]);
                mma16816(sacc[2 * mp + 2], qah[ks], tkb[0], tkb[2]);
                mma16816(sacc[2 * mp + 3], qah[ks], tkb[1], tkb[3]);
                mma16816(sacc[2 * mp],     qal[ks], tka[0], tka[2]);
                mma16816(sacc[2 * mp + 1], qal[ks], tka[1], tka[3]);
                mma16816(sacc[2 * mp + 2], qal[ks], tkb[0], tkb[2]);
                mma16816(sacc[2 * mp + 3], qal[ks], tkb[1], tkb[3]);
                mma16816(sacc[2 * mp],     qah[ks], uka[0], uka[2]);
                mma16816(sacc[2 * mp + 1], qah[ks], uka[1], uka[3]);
                mma16816(sacc[2 * mp + 2], qah[ks], ukb[0], ukb[2]);
                mma16816(sacc[2 * mp + 3], qah[ks], ukb[1], ukb[3]);
            }
        }

        if (kbase + 63 > qr) {
#pragma unroll
            for (int nt = 0; nt < 8; nt++) {
                int kg = kbase + nt * 8 + 2 * tig;
                if (kg > qr)         sacc[nt][0] = -1e30f;
                if (kg + 1 > qr)     sacc[nt][1] = -1e30f;
                if (kg > qr + 8)     sacc[nt][2] = -1e30f;
                if (kg + 1 > qr + 8) sacc[nt][3] = -1e30f;
            }
        }

        // online softmax in exp2 domain
        float ml0 = -1e30f, ml1 = -1e30f;
#pragma unroll
        for (int nt = 0; nt < 8; nt++) {
            ml0 = fmaxf(ml0, fmaxf(sacc[nt][0], sacc[nt][1]));
            ml1 = fmaxf(ml1, fmaxf(sacc[nt][2], sacc[nt][3]));
        }
        ml0 = fmaxf(ml0, __shfl_xor_sync(0xffffffffu, ml0, 1));
        ml0 = fmaxf(ml0, __shfl_xor_sync(0xffffffffu, ml0, 2));
        ml1 = fmaxf(ml1, __shfl_xor_sync(0xffffffffu, ml1, 1));
        ml1 = fmaxf(ml1, __shfl_xor_sync(0xffffffffu, ml1, 2));
        float mn0 = fmaxf(mrun0, ml0), mn1 = fmaxf(mrun1, ml1);
        float scl0 = fexp2(mrun0 - mn0), scl1 = fexp2(mrun1 - mn1);
        mrun0 = mn0; mrun1 = mn1;
        float ls0 = 0.f, ls1 = 0.f;
#pragma unroll
        for (int nt = 0; nt < 8; nt++) {
            float p0 = fexp2(sacc[nt][0] - mn0);
            float p1 = fexp2(sacc[nt][1] - mn0);
            float p2 = fexp2(sacc[nt][2] - mn1);
            float p3 = fexp2(sacc[nt][3] - mn1);
            ls0 += p0 + p1; ls1 += p2 + p3;
            sacc[nt][0] = p0; sacc[nt][1] = p1; sacc[nt][2] = p2; sacc[nt][3] = p3;
            o[nt][0] *= scl0; o[nt][1] *= scl0; o[nt][2] *= scl1; o[nt][3] *= scl1;
        }
        lrun0 = lrun0 * scl0 + ls0;
        lrun1 = lrun1 * scl1 + ls1;

        // P store: fp16, rows warp-private
#pragma unroll
        for (int nt = 0; nt < 8; nt++) {
            Ph[(16 * w + g) * 44 + nt * 4 + tig]     = pack_f16x2(sacc[nt][0], sacc[nt][1]);
            Ph[(16 * w + g + 8) * 44 + nt * 4 + tig] = pack_f16x2(sacc[nt][2], sacc[nt][3]);
        }
        __syncwarp();

        // O += P @ V (single-term fp16 x fp16, f32 accumulate)
#pragma unroll
        for (int ks = 0; ks < 4; ks++) {
            uint32_t ph[4];
            ldsm4(ph, sPh + w * 2816 + ks * 32 + foA);
#pragma unroll
            for (int mp = 0; mp < 4; mp += 2) {
                uint32_t tva[4], tvb[4];
                ldsm4(tva, sV + mp * 2816 + ks * 32 + foA);
                ldsm4(tvb, sV + (mp + 1) * 2816 + ks * 32 + foA);
                mma16816f(o[2 * mp],     ph, tva[0], tva[2]);
                mma16816f(o[2 * mp + 1], ph, tva[1], tva[3]);
                mma16816f(o[2 * mp + 2], ph, tvb[0], tvb[2]);
                mma16816f(o[2 * mp + 3], ph, tvb[1], tvb[3]);
            }
        }
    }

    lrun0 += __shfl_xor_sync(0xffffffffu, lrun0, 1);
    lrun0 += __shfl_xor_sync(0xffffffffu, lrun0, 2);
    lrun1 += __shfl_xor_sync(0xffffffffu, lrun1, 1);
    lrun1 += __shfl_xor_sync(0xffffffffu, lrun1, 2);
    float inv0 = 1.f / lrun0, inv1 = 1.f / lrun1;
    size_t ob0 = ((size_t)bn * SEQ + qr) * 32 + tig;
    size_t ob1 = ((size_t)bn * SEQ + qr + 8) * 32 + tig;
#pragma unroll
    for (int nt = 0; nt < 8; nt++) {
        uint32_t hi, lo;
        split_pack(o[nt][0] * inv0, o[nt][1] * inv0, hi, lo);
        g_Oh[ob0 + nt * 4] = hi;  g_Ol[ob0 + nt * 4] = lo;
        split_pack(o[nt][2] * inv1, o[nt][3] * inv1, hi, lo);
        g_Oh[ob1 + nt * 4] = hi;  g_Ol[ob1 + nt * 4] = lo;
    }
}

extern "C" void kernel_launch(void* const* d_in, const int* in_sizes, int n_in,
                              void* d_out, int out_size)
{
    const float* x    = (const float*)d_in[0];
    const float* pe   = (const float*)d_in[1];
    const float* Wqkv = (const float*)d_in[2];
    const float* Wo   = (const float*)d_in[3];
    float* out = (float*)d_out;

    const int SMEM_DYN = 2 * 40960;
    cudaFuncSetAttribute(qkv_gemm, cudaFuncAttributeMaxDynamicSharedMemorySize, SMEM_DYN);
    cudaFuncSetAttribute(out_gemm, cudaFuncAttributeMaxDynamicSharedMemorySize, SMEM_DYN);
    cudaFuncSetAttribute(attn_kernel, cudaFuncAttributeMaxDynamicSharedMemorySize, ATTN_SMEM);

    cvt_x_kernel<<<(MTOK * 512 + 255) / 256, 256>>>(x, pe);
    cvt_w_kernel<<<(4 * HIDDEN * 512 + 255) / 256, 256>>>(Wqkv, Wo);
    qkv_gemm<<<dim3(3 * HIDDEN / 128, MTOK / 128), 256, SMEM_DYN>>>();
    attn_kernel<<<dim3(BNH, SEQ / 128), 256, ATTN_SMEM>>>();
    out_gemm<<<dim3(HIDDEN / 128, MTOK / 128), 256, SMEM_DYN>>>(out);
}